// round 15
// baseline (speedup 1.0000x reference)
#include <cuda_runtime.h>
#include <cstdint>

// z: [B=2048, TF=120, DL=16]  W: [TF, DL, 672]  bias: [TF, 672]
// out: [B, TF, 16, 43] fp32
#define TF     120
#define DL     16
#define PFEAT  16
#define CHUNK  42
#define RPAD   44           // W smem row: cols 0..41 real, 42..43 junk
#define OUTC   43
#define OPB    (PFEAT*OUTC) // 688 floats = 2752B per (b,t), contiguous
#define BT     16           // batches per tile (each thread: 2 of them)
#define NTH    256          // 8 bl x 16 f x 2 hf
#define SST    692          // staging stride; banks 20*bl+11*fpart -> conflict-free
#define ZPU    18           // z row stride in ull units (16B-aligned rows)
#define TPB    16           // tiles per block (W fill amortized 2x more than R13)

// 10 / tau / ln(2) folded into softmax W columns and bias at fill time:
// exp(10*h) == exp2(h * 10*log2(e))
#define SMSCALE 14.4269504088896341f

typedef unsigned long long ull;

__device__ __forceinline__ ull ffma2(ull a, ull b, ull c) {
    ull d;
    asm("fma.rn.f32x2 %0, %1, %2, %3;" : "=l"(d) : "l"(a), "l"(b), "l"(c));
    return d;
}
__device__ __forceinline__ uint32_t smem_u32(const void* p) {
    uint32_t a;
    asm("{ .reg .u64 t; cvta.to.shared.u64 t, %1; cvt.u32.u64 %0, t; }"
        : "=r"(a) : "l"(p));
    return a;
}
__device__ __forceinline__ void bulk_s2g(void* gdst, uint32_t ssrc, uint32_t bytes) {
    asm volatile("cp.async.bulk.global.shared::cta.bulk_group [%0], [%1], %2;"
                 :: "l"(gdst), "r"(ssrc), "r"(bytes) : "memory");
}
__device__ __forceinline__ float softplus_f(float x) {
    return fmaxf(x, 0.f) + __logf(1.f + __expf(-fabsf(x)));
}

// GEMM over Q ulonglong2 column-groups x 2 batches; z read as LDS.128 k-pairs.
template<int Q>
__device__ __forceinline__ void gemm2(ull* accA, ull* accB,
                                      const ulonglong2* zA2, const ulonglong2* zB2,
                                      const float* wbase, const ulonglong2* bini)
{
    #pragma unroll
    for (int q = 0; q < Q; q++) {
        ulonglong2 v = bini[q];
        accA[2 * q] = v.x;  accA[2 * q + 1] = v.y;
        accB[2 * q] = v.x;  accB[2 * q + 1] = v.y;
    }
    #pragma unroll
    for (int kp = 0; kp < DL / 2; kp++) {
        ulonglong2 zpa = zA2[kp];            // (z[2kp] dup, z[2kp+1] dup) batch A
        ulonglong2 zpb = zB2[kp];            // batch B
        const ulonglong2* w0 =
            reinterpret_cast<const ulonglong2*>(wbase + (2 * kp) * (PFEAT * RPAD));
        const ulonglong2* w1 =
            reinterpret_cast<const ulonglong2*>(wbase + (2 * kp + 1) * (PFEAT * RPAD));
        #pragma unroll
        for (int q = 0; q < Q; q++) {        // one W load feeds 4 ffma2
            ulonglong2 w = w0[q];
            accA[2 * q]     = ffma2(zpa.x, w.x, accA[2 * q]);
            accA[2 * q + 1] = ffma2(zpa.x, w.y, accA[2 * q + 1]);
            accB[2 * q]     = ffma2(zpb.x, w.x, accB[2 * q]);
            accB[2 * q + 1] = ffma2(zpb.x, w.y, accB[2 * q + 1]);
        }
        #pragma unroll
        for (int q = 0; q < Q; q++) {
            ulonglong2 w = w1[q];
            accA[2 * q]     = ffma2(zpa.y, w.x, accA[2 * q]);
            accA[2 * q + 1] = ffma2(zpa.y, w.y, accA[2 * q + 1]);
            accB[2 * q]     = ffma2(zpb.y, w.x, accB[2 * q]);
            accB[2 * q + 1] = ffma2(zpb.y, w.y, accB[2 * q + 1]);
        }
    }
}

__global__ __launch_bounds__(NTH, 2)
void ddm_spline_kernel(const float* __restrict__ z,
                       const float* __restrict__ W,
                       const float* __restrict__ bias,
                       float* __restrict__ out)
{
    extern __shared__ float smem[];
    float* Ws  = smem;                                      // 11264 floats
    float* bs  = Ws + DL * PFEAT * RPAD;                    // 704
    ull*   zu  = reinterpret_cast<ull*>(bs + PFEAT * RPAD); // 2 x [BT][ZPU] ull
    float* stg = reinterpret_cast<float*>(zu + 2 * BT * ZPU); // [BT][SST]

    const int tid = threadIdx.x;
    const int t   = blockIdx.y;
    const int bb0 = blockIdx.x * (BT * TPB);
    const int bl  = tid & 7;           // batch slot (thread also handles bl+8)
    const int f   = (tid >> 3) & 15;   // feature
    const int hf  = tid >> 7;          // 0: cols 0..19, 1: cols 20..43
    const int wrp = tid >> 5;          // warp id (0..7): flush rows wrp, wrp+8
    const int ln  = tid & 31;

    // ---- W[t] -> smem; softmax cols (j>=22) pre-scaled by 10*log2(e) ----
    const float* Wt = W + (size_t)t * (DL * PFEAT * CHUNK);
    for (int it = 0; it < (DL * PFEAT * CHUNK) / NTH; it++) {   // 42 exact
        int i  = tid + it * NTH;
        int k  = i / (PFEAT * CHUNK);
        int r  = i - k * (PFEAT * CHUNK);
        int ff = r / CHUNK;
        int j  = r - ff * CHUNK;
        float v = Wt[i];
        if (j >= 22) v *= SMSCALE;
        Ws[(k * PFEAT + ff) * RPAD + j] = v;
    }
    {   // bias[t], same scaling
        const float* bt = bias + (size_t)t * (PFEAT * CHUNK);
        for (int i = tid; i < PFEAT * CHUNK; i += NTH) {
            int ff = i / CHUNK;
            int j  = i - ff * CHUNK;
            float v = bt[i];
            if (j >= 22) v *= SMSCALE;
            bs[ff * RPAD + j] = v;
        }
    }
    // ---- z for tile 0 into buffer 0 (duplicated f32x2, rows stride 18 ull) ----
    const int zbb = tid >> 4, zkk = tid & 15;    // BT*DL == NTH
    {
        float zv = __ldcs(&z[((size_t)(bb0 + zbb) * TF + t) * DL + zkk]);
        reinterpret_cast<float2*>(zu)[zbb * ZPU + zkk] = make_float2(zv, zv);
    }
    __syncthreads();

    // steady-state base pointers
    const float* wbase = Ws + f * RPAD + hf * 20;                 // 80B offset, 16B-aligned
    const ulonglong2* bini =
        reinterpret_cast<const ulonglong2*>(bs + f * RPAD + hf * 20);
    float* srowA = stg + bl * SST + f * OUTC + hf * 20;
    float* srowB = srowA + 8 * SST;
    const uint32_t stg_sA = smem_u32(stg + wrp * SST);
    const uint32_t stg_sB = smem_u32(stg + (wrp + 8) * SST);

    for (int tile = 0; tile < TPB; tile++) {
        const int b0 = bb0 + tile * BT;

        // prefetch z for tile+1 into a register
        float zv_next = 0.f;
        if (tile + 1 < TPB)
            zv_next = __ldcs(&z[((size_t)(b0 + BT + zbb) * TF + t) * DL + zkk]);

        const ull* zbuf = zu + (tile & 1) * (BT * ZPU);
        const ulonglong2* zA2 =
            reinterpret_cast<const ulonglong2*>(zbuf + bl * ZPU);
        const ulonglong2* zB2 =
            reinterpret_cast<const ulonglong2*>(zbuf + (bl + 8) * ZPU);

        // ---- GEMM (overlaps prior tile's bulk-store drain) ----
        ull accA[12], accB[12];
        if (hf == 0) gemm2<5>(accA, accB, zA2, zB2, wbase, bini);  // cols 0..19
        else         gemm2<6>(accA, accB, zA2, zB2, wbase, bini);  // cols 20..43

        // previous tile's bulk stores must be done READING stg before we overwrite it
        if (ln == 0)
            asm volatile("cp.async.bulk.wait_group.read 0;" ::: "memory");
        __syncthreads();

        // ---- transforms (both batches) -> staging ----
        #pragma unroll
        for (int which = 0; which < 2; which++) {
            const ull* acc = which ? accB : accA;
            float* srow = which ? srowB : srowA;
            if (hf == 0) {
                float hh[20];
                #pragma unroll
                for (int q = 0; q < 10; q++) {
                    float2 v = *reinterpret_cast<const float2*>(&acc[q]);
                    hh[2 * q] = v.x; hh[2 * q + 1] = v.y;
                }
                srow[0] = hh[0];                                  // gamma
                #pragma unroll
                for (int i = 1; i < 20; i++)                      // beta 1..19
                    srow[i] = softplus_f(hh[i]);
            } else {
                float hh[24];
                #pragma unroll
                for (int q = 0; q < 12; q++) {
                    float2 v = *reinterpret_cast<const float2*>(&acc[q]);
                    hh[2 * q] = v.x; hh[2 * q + 1] = v.y;
                }
                srow[0] = softplus_f(hh[0]);                      // beta 20
                srow[1] = softplus_f(hh[1]);                      // beta 21
                // logits pre-scaled by 10*log2(e) in W/bias -> bare exp2, no-max safe
                float e[20];
                float sum = 0.f;
                #pragma unroll
                for (int i = 0; i < 20; i++) {
                    e[i] = exp2f(hh[2 + i]);
                    sum += e[i];
                }
                float inv = __fdividef(1.0f, sum);
                srow[2] = 0.f;                                    // delta_0
                float c = 0.f;
                #pragma unroll
                for (int i = 0; i < 20; i++) {
                    c += e[i];
                    srow[3 + i] = c * inv;
                }
            }
        }

        // z for next tile -> other buffer (readers finished before the barrier above)
        if (tile + 1 < TPB) {
            float2* zn = reinterpret_cast<float2*>(zu + ((tile + 1) & 1) * (BT * ZPU));
            zn[zbb * ZPU + zkk] = make_float2(zv_next, zv_next);
        }

        asm volatile("fence.proxy.async.shared::cta;" ::: "memory");
        __syncthreads();   // staging complete + visible to async proxy

        // ---- flush via bulk copy engine: warp w issues rows w and w+8 ----
        if (ln == 0) {
            bulk_s2g(out + ((size_t)(b0 + wrp) * TF + t) * OPB,     stg_sA, OPB * 4);
            bulk_s2g(out + ((size_t)(b0 + wrp + 8) * TF + t) * OPB, stg_sB, OPB * 4);
            asm volatile("cp.async.bulk.commit_group;" ::: "memory");
        }
    }
    if (ln == 0)
        asm volatile("cp.async.bulk.wait_group 0;" ::: "memory");
}

extern "C" void kernel_launch(void* const* d_in, const int* in_sizes, int n_in,
                              void* d_out, int out_size) {
    const float* z    = (const float*)d_in[0];
    const float* W    = (const float*)d_in[1];
    const float* bias = (const float*)d_in[2];
    float* out        = (float*)d_out;

    const int B = in_sizes[0] / (TF * DL);    // 2048
    const int splits = B / (BT * TPB);        // 8

    const size_t shmem =
        (size_t)(DL * PFEAT * RPAD + PFEAT * RPAD + 2 * BT * ZPU * 2 + BT * SST)
        * sizeof(float);

    cudaFuncSetAttribute(ddm_spline_kernel,
                         cudaFuncAttributeMaxDynamicSharedMemorySize, (int)shmem);

    dim3 grid(splits, TF);
    ddm_spline_kernel<<<grid, NTH, shmem>>>(z, W, bias, out);
}

// round 16
// speedup vs baseline: 1.0258x; 1.0258x over previous
#include <cuda_runtime.h>
#include <cstdint>

// z: [B=2048, TF=120, DL=16]  W: [TF, DL, 672]  bias: [TF, 672]
// out: [B, TF, 16, 43] fp32
#define TF     120
#define DL     16
#define PFEAT  16
#define CHUNK  42
#define RPAD   44           // W smem row: cols 0..41 real, 42..43 junk
#define OUTC   43
#define OPB    (PFEAT*OUTC) // 688 floats = 2752B per (b,t), contiguous
#define BT     16           // batches per tile (each thread: 2 of them)
#define NTH    256          // 8 bl x 16 f x 2 hf
#define SST    692          // staging stride; conflict-free STS
#define ZPU    18           // z row stride in ull units (16B-aligned rows)
#define TPB    8            // tiles per block (1920 blocks: better wave quantization)

// fill-time scale folds:
//   beta cols (1..21):    * log2(e)        -> softplus computed in log2 domain
//   softmax cols (22..41):* 10*log2(e)     -> bare exp2 in transform (tau=0.1)
#define LOG2E   1.4426950408889634f
#define SMSCALE 14.4269504088896341f
#define LN2     0.6931471805599453f

typedef unsigned long long ull;

__device__ __forceinline__ ull ffma2(ull a, ull b, ull c) {
    ull d;
    asm("fma.rn.f32x2 %0, %1, %2, %3;" : "=l"(d) : "l"(a), "l"(b), "l"(c));
    return d;
}
__device__ __forceinline__ uint32_t smem_u32(const void* p) {
    uint32_t a;
    asm("{ .reg .u64 t; cvta.to.shared.u64 t, %1; cvt.u32.u64 %0, t; }"
        : "=r"(a) : "l"(p));
    return a;
}
__device__ __forceinline__ void bulk_s2g(void* gdst, uint32_t ssrc, uint32_t bytes) {
    asm volatile("cp.async.bulk.global.shared::cta.bulk_group [%0], [%1], %2;"
                 :: "l"(gdst), "r"(ssrc), "r"(bytes) : "memory");
}
// softplus in log2 domain: input y = x*log2(e); returns softplus(x)
__device__ __forceinline__ float softplus2_f(float y) {
    float e = exp2f(-fabsf(y));                 // MUFU.EX2 with neg-abs operand
    float l = __log2f(1.f + e);                 // MUFU.LG2
    return LN2 * (fmaxf(y, 0.f) + l);
}

// GEMM over Q ulonglong2 column-groups x 2 batches; z read as LDS.128 k-pairs.
template<int Q>
__device__ __forceinline__ void gemm2(ull* accA, ull* accB,
                                      const ulonglong2* zA2, const ulonglong2* zB2,
                                      const float* wbase, const ulonglong2* bini)
{
    #pragma unroll
    for (int q = 0; q < Q; q++) {
        ulonglong2 v = bini[q];
        accA[2 * q] = v.x;  accA[2 * q + 1] = v.y;
        accB[2 * q] = v.x;  accB[2 * q + 1] = v.y;
    }
    #pragma unroll
    for (int kp = 0; kp < DL / 2; kp++) {
        ulonglong2 zpa = zA2[kp];            // (z[2kp] dup, z[2kp+1] dup) batch A
        ulonglong2 zpb = zB2[kp];            // batch B
        const ulonglong2* w0 =
            reinterpret_cast<const ulonglong2*>(wbase + (2 * kp) * (PFEAT * RPAD));
        const ulonglong2* w1 =
            reinterpret_cast<const ulonglong2*>(wbase + (2 * kp + 1) * (PFEAT * RPAD));
        #pragma unroll
        for (int q = 0; q < Q; q++) {        // one W load feeds 4 ffma2
            ulonglong2 w = w0[q];
            accA[2 * q]     = ffma2(zpa.x, w.x, accA[2 * q]);
            accA[2 * q + 1] = ffma2(zpa.x, w.y, accA[2 * q + 1]);
            accB[2 * q]     = ffma2(zpb.x, w.x, accB[2 * q]);
            accB[2 * q + 1] = ffma2(zpb.x, w.y, accB[2 * q + 1]);
        }
        #pragma unroll
        for (int q = 0; q < Q; q++) {
            ulonglong2 w = w1[q];
            accA[2 * q]     = ffma2(zpa.y, w.x, accA[2 * q]);
            accA[2 * q + 1] = ffma2(zpa.y, w.y, accA[2 * q + 1]);
            accB[2 * q]     = ffma2(zpb.y, w.x, accB[2 * q]);
            accB[2 * q + 1] = ffma2(zpb.y, w.y, accB[2 * q + 1]);
        }
    }
}

__global__ __launch_bounds__(NTH, 2)
void ddm_spline_kernel(const float* __restrict__ z,
                       const float* __restrict__ W,
                       const float* __restrict__ bias,
                       float* __restrict__ out)
{
    extern __shared__ float smem[];
    float* Ws  = smem;                                      // 11264 floats
    float* bs  = Ws + DL * PFEAT * RPAD;                    // 704
    ull*   zu  = reinterpret_cast<ull*>(bs + PFEAT * RPAD); // 2 x [BT][ZPU] ull
    float* stg = reinterpret_cast<float*>(zu + 2 * BT * ZPU); // [BT][SST]

    const int tid = threadIdx.x;
    const int t   = blockIdx.y;
    const int bb0 = blockIdx.x * (BT * TPB);
    const int bl  = tid & 7;           // batch slot (thread also handles bl+8)
    const int f   = (tid >> 3) & 15;   // feature
    const int hf  = tid >> 7;          // 0: cols 0..19, 1: cols 20..43
    const int wrp = tid >> 5;          // warp id (0..7): flush rows wrp, wrp+8
    const int ln  = tid & 31;

    // ---- W[t] -> smem with per-column scale folds (once per block) ----
    const float* Wt = W + (size_t)t * (DL * PFEAT * CHUNK);
    for (int it = 0; it < (DL * PFEAT * CHUNK) / NTH; it++) {   // 42 exact
        int i  = tid + it * NTH;
        int k  = i / (PFEAT * CHUNK);
        int r  = i - k * (PFEAT * CHUNK);
        int ff = r / CHUNK;
        int j  = r - ff * CHUNK;
        float v = Wt[i];
        float s = (j == 0) ? 1.f : ((j < 22) ? LOG2E : SMSCALE);
        Ws[(k * PFEAT + ff) * RPAD + j] = v * s;
    }
    {   // bias[t], same scaling
        const float* bt = bias + (size_t)t * (PFEAT * CHUNK);
        for (int i = tid; i < PFEAT * CHUNK; i += NTH) {
            int ff = i / CHUNK;
            int j  = i - ff * CHUNK;
            float v = bt[i];
            float s = (j == 0) ? 1.f : ((j < 22) ? LOG2E : SMSCALE);
            bs[ff * RPAD + j] = v * s;
        }
    }
    // ---- z for tile 0 into buffer 0 (duplicated f32x2, rows stride 18 ull) ----
    const int zbb = tid >> 4, zkk = tid & 15;    // BT*DL == NTH
    {
        float zv = __ldcs(&z[((size_t)(bb0 + zbb) * TF + t) * DL + zkk]);
        reinterpret_cast<float2*>(zu)[zbb * ZPU + zkk] = make_float2(zv, zv);
    }
    __syncthreads();

    // steady-state base pointers
    const float* wbase = Ws + f * RPAD + hf * 20;                 // 80B offset, 16B-aligned
    const ulonglong2* bini =
        reinterpret_cast<const ulonglong2*>(bs + f * RPAD + hf * 20);
    float* srowA = stg + bl * SST + f * OUTC + hf * 20;
    float* srowB = srowA + 8 * SST;
    const uint32_t stg_sA = smem_u32(stg + wrp * SST);
    const uint32_t stg_sB = smem_u32(stg + (wrp + 8) * SST);

    for (int tile = 0; tile < TPB; tile++) {
        const int b0 = bb0 + tile * BT;

        // prefetch z for tile+1 into a register
        float zv_next = 0.f;
        if (tile + 1 < TPB)
            zv_next = __ldcs(&z[((size_t)(b0 + BT + zbb) * TF + t) * DL + zkk]);

        const ull* zbuf = zu + (tile & 1) * (BT * ZPU);
        const ulonglong2* zA2 =
            reinterpret_cast<const ulonglong2*>(zbuf + bl * ZPU);
        const ulonglong2* zB2 =
            reinterpret_cast<const ulonglong2*>(zbuf + (bl + 8) * ZPU);

        // ---- GEMM (overlaps prior tile's bulk-store drain) ----
        ull accA[12], accB[12];
        if (hf == 0) gemm2<5>(accA, accB, zA2, zB2, wbase, bini);  // cols 0..19
        else         gemm2<6>(accA, accB, zA2, zB2, wbase, bini);  // cols 20..43

        // previous tile's bulk stores must be done READING stg before we overwrite it
        if (ln == 0)
            asm volatile("cp.async.bulk.wait_group.read 0;" ::: "memory");
        __syncthreads();

        // ---- transforms (both batches) -> staging ----
        #pragma unroll
        for (int which = 0; which < 2; which++) {
            const ull* acc = which ? accB : accA;
            float* srow = which ? srowB : srowA;
            if (hf == 0) {
                float hh[20];
                #pragma unroll
                for (int q = 0; q < 10; q++) {
                    float2 v = *reinterpret_cast<const float2*>(&acc[q]);
                    hh[2 * q] = v.x; hh[2 * q + 1] = v.y;
                }
                srow[0] = hh[0];                                  // gamma (unscaled)
                #pragma unroll
                for (int i = 1; i < 20; i++)                      // beta 1..19 (log2 domain)
                    srow[i] = softplus2_f(hh[i]);
            } else {
                float hh[24];
                #pragma unroll
                for (int q = 0; q < 12; q++) {
                    float2 v = *reinterpret_cast<const float2*>(&acc[q]);
                    hh[2 * q] = v.x; hh[2 * q + 1] = v.y;
                }
                srow[0] = softplus2_f(hh[0]);                     // beta 20
                srow[1] = softplus2_f(hh[1]);                     // beta 21
                // logits pre-scaled by 10*log2(e): bare exp2, no-max safe (bounded)
                float e[20];
                float sum = 0.f;
                #pragma unroll
                for (int i = 0; i < 20; i++) {
                    e[i] = exp2f(hh[2 + i]);
                    sum += e[i];
                }
                float inv = __fdividef(1.0f, sum);
                srow[2] = 0.f;                                    // delta_0
                float c = 0.f;
                #pragma unroll
                for (int i = 0; i < 20; i++) {
                    c += e[i];
                    srow[3 + i] = c * inv;
                }
            }
        }

        // z for next tile -> other buffer (readers finished before the barrier above)
        if (tile + 1 < TPB) {
            float2* zn = reinterpret_cast<float2*>(zu + ((tile + 1) & 1) * (BT * ZPU));
            zn[zbb * ZPU + zkk] = make_float2(zv_next, zv_next);
        }

        asm volatile("fence.proxy.async.shared::cta;" ::: "memory");
        __syncthreads();   // staging complete + visible to async proxy

        // ---- flush via bulk copy engine: warp w issues rows w and w+8 ----
        if (ln == 0) {
            bulk_s2g(out + ((size_t)(b0 + wrp) * TF + t) * OPB,     stg_sA, OPB * 4);
            bulk_s2g(out + ((size_t)(b0 + wrp + 8) * TF + t) * OPB, stg_sB, OPB * 4);
            asm volatile("cp.async.bulk.commit_group;" ::: "memory");
        }
    }
    if (ln == 0)
        asm volatile("cp.async.bulk.wait_group 0;" ::: "memory");
}

extern "C" void kernel_launch(void* const* d_in, const int* in_sizes, int n_in,
                              void* d_out, int out_size) {
    const float* z    = (const float*)d_in[0];
    const float* W    = (const float*)d_in[1];
    const float* bias = (const float*)d_in[2];
    float* out        = (float*)d_out;

    const int B = in_sizes[0] / (TF * DL);    // 2048
    const int splits = B / (BT * TPB);        // 16

    const size_t shmem =
        (size_t)(DL * PFEAT * RPAD + PFEAT * RPAD + 2 * BT * ZPU * 2 + BT * SST)
        * sizeof(float);

    cudaFuncSetAttribute(ddm_spline_kernel,
                         cudaFuncAttributeMaxDynamicSharedMemorySize, (int)shmem);

    dim3 grid(splits, TF);
    ddm_spline_kernel<<<grid, NTH, shmem>>>(z, W, bias, out);
}

// round 17
// speedup vs baseline: 1.0283x; 1.0025x over previous
#include <cuda_runtime.h>
#include <cstdint>

// z: [B=2048, TF=120, DL=16]  W: [TF, DL, 672]  bias: [TF, 672]
// out: [B, TF, 16, 43] fp32
#define TF     120
#define DL     16
#define PFEAT  16
#define CHUNK  42
#define RPAD   44           // W smem row: cols 0..41 real, 42..43 junk
#define OUTC   43
#define OPB    (PFEAT*OUTC) // 688 floats = 2752B per (b,t), contiguous
#define BT     16           // batches per tile (each thread: 2 of them)
#define NTH    256          // 8 bl x 16 f x 2 hf
#define SST    692          // staging stride; conflict-free STS
#define ZPU    18           // z row stride in ull units (16B-aligned rows)
#define TPB    8            // tiles per block

// fill-time scale folds:
//   beta cols (1..21):     * log2(e)   -> softplus computed in log2 domain
//   softmax cols (22..41): * 10*log2(e)-> bare exp2 in transform (tau=0.1)
#define LOG2E   1.4426950408889634f
#define SMSCALE 14.4269504088896341f
#define LN2     0.6931471805599453f

typedef unsigned long long ull;

__device__ __forceinline__ ull ffma2(ull a, ull b, ull c) {
    ull d;
    asm("fma.rn.f32x2 %0, %1, %2, %3;" : "=l"(d) : "l"(a), "l"(b), "l"(c));
    return d;
}
__device__ __forceinline__ uint32_t smem_u32(const void* p) {
    uint32_t a;
    asm("{ .reg .u64 t; cvta.to.shared.u64 t, %1; cvt.u32.u64 %0, t; }"
        : "=r"(a) : "l"(p));
    return a;
}
__device__ __forceinline__ void bulk_s2g(void* gdst, uint32_t ssrc, uint32_t bytes) {
    asm volatile("cp.async.bulk.global.shared::cta.bulk_group [%0], [%1], %2;"
                 :: "l"(gdst), "r"(ssrc), "r"(bytes) : "memory");
}
// independent 16B shared load (volatile: not CSE'd against the twin load)
__device__ __forceinline__ void lds_v2u64(ull& lo, ull& hi, uint32_t addr) {
    asm volatile("ld.shared.v2.u64 {%0, %1}, [%2];"
                 : "=l"(lo), "=l"(hi) : "r"(addr));
}
// softplus in log2 domain: input y = x*log2(e); returns softplus(x)
__device__ __forceinline__ float softplus2_f(float y) {
    float e = exp2f(-fabsf(y));                 // MUFU.EX2 (operand mods free)
    float l = __log2f(1.f + e);                 // MUFU.LG2
    return LN2 * (fmaxf(y, 0.f) + l);
}

// GEMM over Q ulonglong2 column-groups x 2 batches; z read as LDS.128 k-pairs.
// Accumulators initialized straight from shared (two independent loads, no copies).
template<int Q>
__device__ __forceinline__ void gemm2(ull* accA, ull* accB,
                                      const ulonglong2* zA2, const ulonglong2* zB2,
                                      const float* wbase, uint32_t bini_s)
{
    #pragma unroll
    for (int q = 0; q < Q; q++)
        lds_v2u64(accA[2 * q], accA[2 * q + 1], bini_s + 16u * q);
    #pragma unroll
    for (int q = 0; q < Q; q++)
        lds_v2u64(accB[2 * q], accB[2 * q + 1], bini_s + 16u * q);

    #pragma unroll
    for (int kp = 0; kp < DL / 2; kp++) {
        ulonglong2 zpa = zA2[kp];            // (z[2kp] dup, z[2kp+1] dup) batch A
        ulonglong2 zpb = zB2[kp];            // batch B
        const ulonglong2* w0 =
            reinterpret_cast<const ulonglong2*>(wbase + (2 * kp) * (PFEAT * RPAD));
        const ulonglong2* w1 =
            reinterpret_cast<const ulonglong2*>(wbase + (2 * kp + 1) * (PFEAT * RPAD));
        #pragma unroll
        for (int q = 0; q < Q; q++) {        // one W load feeds 4 ffma2
            ulonglong2 w = w0[q];
            accA[2 * q]     = ffma2(zpa.x, w.x, accA[2 * q]);
            accA[2 * q + 1] = ffma2(zpa.x, w.y, accA[2 * q + 1]);
            accB[2 * q]     = ffma2(zpb.x, w.x, accB[2 * q]);
            accB[2 * q + 1] = ffma2(zpb.x, w.y, accB[2 * q + 1]);
        }
        #pragma unroll
        for (int q = 0; q < Q; q++) {
            ulonglong2 w = w1[q];
            accA[2 * q]     = ffma2(zpa.y, w.x, accA[2 * q]);
            accA[2 * q + 1] = ffma2(zpa.y, w.y, accA[2 * q + 1]);
            accB[2 * q]     = ffma2(zpb.y, w.x, accB[2 * q]);
            accB[2 * q + 1] = ffma2(zpb.y, w.y, accB[2 * q + 1]);
        }
    }
}

__global__ __launch_bounds__(NTH, 2)
void ddm_spline_kernel(const float* __restrict__ z,
                       const float* __restrict__ W,
                       const float* __restrict__ bias,
                       float* __restrict__ out)
{
    extern __shared__ float smem[];
    float* Ws  = smem;                                      // 11264 floats
    float* bs  = Ws + DL * PFEAT * RPAD;                    // 704
    ull*   zu  = reinterpret_cast<ull*>(bs + PFEAT * RPAD); // 2 x [BT][ZPU] ull
    float* stg = reinterpret_cast<float*>(zu + 2 * BT * ZPU); // [BT][SST]

    const int tid = threadIdx.x;
    const int t   = blockIdx.y;
    const int bb0 = blockIdx.x * (BT * TPB);
    const int bl  = tid & 7;           // batch slot (thread also handles bl+8)
    const int f   = (tid >> 3) & 15;   // feature
    const int hf  = tid >> 7;          // 0: cols 0..19, 1: cols 20..43
    const int wrp = tid >> 5;          // warp id (0..7): flush rows wrp, wrp+8
    const int ln  = tid & 31;

    // ---- W[t] -> smem with per-column scale folds (unsigned index math) ----
    const float* Wt = W + (size_t)t * (DL * PFEAT * CHUNK);
    for (unsigned it = 0; it < (DL * PFEAT * CHUNK) / NTH; it++) {   // 42 exact
        unsigned i  = (unsigned)tid + it * NTH;
        unsigned k  = i / (PFEAT * CHUNK);
        unsigned r  = i - k * (PFEAT * CHUNK);
        unsigned ff = r / CHUNK;
        unsigned j  = r - ff * CHUNK;
        float v = Wt[i];
        float s = (j == 0) ? 1.f : ((j < 22) ? LOG2E : SMSCALE);
        Ws[(k * PFEAT + ff) * RPAD + j] = v * s;
    }
    {   // bias[t], same scaling
        const float* bt = bias + (size_t)t * (PFEAT * CHUNK);
        for (unsigned i = (unsigned)tid; i < PFEAT * CHUNK; i += NTH) {
            unsigned ff = i / CHUNK;
            unsigned j  = i - ff * CHUNK;
            float v = bt[i];
            float s = (j == 0) ? 1.f : ((j < 22) ? LOG2E : SMSCALE);
            bs[ff * RPAD + j] = v * s;
        }
    }
    // ---- z for tile 0 into buffer 0 (duplicated f32x2, rows stride 18 ull) ----
    const int zbb = tid >> 4, zkk = tid & 15;    // BT*DL == NTH
    {
        float zv = __ldcs(&z[((size_t)(bb0 + zbb) * TF + t) * DL + zkk]);
        reinterpret_cast<float2*>(zu)[zbb * ZPU + zkk] = make_float2(zv, zv);
    }
    __syncthreads();

    // steady-state base pointers
    const float* wbase = Ws + f * RPAD + hf * 20;                 // 80B offset, 16B-aligned
    const uint32_t bini_s = smem_u32(bs + f * RPAD + hf * 20);
    float* srowA = stg + bl * SST + f * OUTC + hf * 20;
    float* srowB = srowA + 8 * SST;
    const uint32_t stg_sA = smem_u32(stg + wrp * SST);
    const uint32_t stg_sB = smem_u32(stg + (wrp + 8) * SST);

    for (int tile = 0; tile < TPB; tile++) {
        const int b0 = bb0 + tile * BT;

        // prefetch z for tile+1 into a register
        float zv_next = 0.f;
        if (tile + 1 < TPB)
            zv_next = __ldcs(&z[((size_t)(b0 + BT + zbb) * TF + t) * DL + zkk]);

        const ull* zbuf = zu + (tile & 1) * (BT * ZPU);
        const ulonglong2* zA2 =
            reinterpret_cast<const ulonglong2*>(zbuf + bl * ZPU);
        const ulonglong2* zB2 =
            reinterpret_cast<const ulonglong2*>(zbuf + (bl + 8) * ZPU);

        // ---- GEMM (overlaps prior tile's bulk-store drain) ----
        ull accA[12], accB[12];
        if (hf == 0) gemm2<5>(accA, accB, zA2, zB2, wbase, bini_s);  // cols 0..19
        else         gemm2<6>(accA, accB, zA2, zB2, wbase, bini_s);  // cols 20..43

        // previous tile's bulk stores must be done READING stg before we overwrite it
        if (ln == 0)
            asm volatile("cp.async.bulk.wait_group.read 0;" ::: "memory");
        __syncthreads();

        // ---- transforms (both batches) -> staging ----
        #pragma unroll
        for (int which = 0; which < 2; which++) {
            const ull* acc = which ? accB : accA;
            float* srow = which ? srowB : srowA;
            if (hf == 0) {
                float hh[20];
                #pragma unroll
                for (int q = 0; q < 10; q++) {
                    float2 v = *reinterpret_cast<const float2*>(&acc[q]);
                    hh[2 * q] = v.x; hh[2 * q + 1] = v.y;
                }
                srow[0] = hh[0];                                  // gamma (unscaled)
                #pragma unroll
                for (int i = 1; i < 20; i++)                      // beta 1..19 (log2 domain)
                    srow[i] = softplus2_f(hh[i]);
            } else {
                float hh[24];
                #pragma unroll
                for (int q = 0; q < 12; q++) {
                    float2 v = *reinterpret_cast<const float2*>(&acc[q]);
                    hh[2 * q] = v.x; hh[2 * q + 1] = v.y;
                }
                srow[0] = softplus2_f(hh[0]);                     // beta 20
                srow[1] = softplus2_f(hh[1]);                     // beta 21
                // logits pre-scaled by 10*log2(e): bare exp2, no-max safe
                float e[20];
                #pragma unroll
                for (int i = 0; i < 20; i++)
                    e[i] = exp2f(hh[2 + i]);
                // tree-structured sum (depth 5, not 20)
                float t0[10];
                #pragma unroll
                for (int i = 0; i < 10; i++) t0[i] = e[2 * i] + e[2 * i + 1];
                float t1[5];
                #pragma unroll
                for (int i = 0; i < 5; i++)  t1[i] = t0[2 * i] + t0[2 * i + 1];
                float sum = ((t1[0] + t1[1]) + (t1[2] + t1[3])) + t1[4];
                float inv = __fdividef(1.0f, sum);
                srow[2] = 0.f;                                    // delta_0
                float c = 0.f;
                #pragma unroll
                for (int i = 0; i < 20; i++) {
                    c += e[i];
                    srow[3 + i] = c * inv;
                }
            }
        }

        // z for next tile -> other buffer (readers finished before the barrier above)
        if (tile + 1 < TPB) {
            float2* zn = reinterpret_cast<float2*>(zu + ((tile + 1) & 1) * (BT * ZPU));
            zn[zbb * ZPU + zkk] = make_float2(zv_next, zv_next);
        }

        asm volatile("fence.proxy.async.shared::cta;" ::: "memory");
        __syncthreads();   // staging complete + visible to async proxy

        // ---- flush via bulk copy engine: warp w issues rows w and w+8 ----
        if (ln == 0) {
            bulk_s2g(out + ((size_t)(b0 + wrp) * TF + t) * OPB,     stg_sA, OPB * 4);
            bulk_s2g(out + ((size_t)(b0 + wrp + 8) * TF + t) * OPB, stg_sB, OPB * 4);
            asm volatile("cp.async.bulk.commit_group;" ::: "memory");
        }
    }
    if (ln == 0)
        asm volatile("cp.async.bulk.wait_group 0;" ::: "memory");
}

extern "C" void kernel_launch(void* const* d_in, const int* in_sizes, int n_in,
                              void* d_out, int out_size) {
    const float* z    = (const float*)d_in[0];
    const float* W    = (const float*)d_in[1];
    const float* bias = (const float*)d_in[2];
    float* out        = (float*)d_out;

    const int B = in_sizes[0] / (TF * DL);    // 2048
    const int splits = B / (BT * TPB);        // 16

    const size_t shmem =
        (size_t)(DL * PFEAT * RPAD + PFEAT * RPAD + 2 * BT * ZPU * 2 + BT * SST)
        * sizeof(float);

    cudaFuncSetAttribute(ddm_spline_kernel,
                         cudaFuncAttributeMaxDynamicSharedMemorySize, (int)shmem);

    dim3 grid(splits, TF);
    ddm_spline_kernel<<<grid, NTH, shmem>>>(z, W, bias, out);
}